// round 1
// baseline (speedup 1.0000x reference)
#include <cuda_runtime.h>

// Tiny-ViT fully fused forward.
// Mapping: 1 image = 64 threads (2 warps); thread t owns token t (t<50).
// Token activation x[8] lives in registers through all 4 transformer blocks.
// Shared memory: all weights (staged once per CTA) + per-image K/V tiles.

namespace {
constexpr int NB   = 4;    // transformer blocks
constexpr int TT   = 50;   // tokens
constexpr int IMGS = 4;    // images per CTA
constexpr int TPI  = 64;   // threads per image
constexpr int NTH  = IMGS * TPI;  // 256

struct SW {
  float linW[128];          // [8][16]
  float cls[8];
  float pos[TT * 8];
  float ln1g[NB * 8], ln1b[NB * 8];
  float Wq[NB * 64], Wk[NB * 64], Wv[NB * 64];
  float projW[NB * 64], projb[NB * 8];
  float ln2g[NB * 8], ln2b[NB * 8];
  float W1[NB * 256], b1[NB * 32];  // W1 [32][8]
  float W2t[NB * 256], b2[NB * 8];  // W2 transposed -> [32][8]
  float mlpW[80], mlpb[12];
};
}  // namespace

__device__ __forceinline__ float dot8(const float* a, const float* w) {
  float s = 0.f;
#pragma unroll
  for (int j = 0; j < 8; j++) s = fmaf(a[j], w[j], s);
  return s;
}

__global__ void __launch_bounds__(NTH) vit_kernel(
    const float* __restrict__ images, const float* __restrict__ cls_g,
    const float* __restrict__ linW_g, const float* __restrict__ ln1g_g,
    const float* __restrict__ ln1b_g, const float* __restrict__ Wq_g,
    const float* __restrict__ Wk_g, const float* __restrict__ Wv_g,
    const float* __restrict__ projW_g, const float* __restrict__ projb_g,
    const float* __restrict__ ln2g_g, const float* __restrict__ ln2b_g,
    const float* __restrict__ W1_g, const float* __restrict__ b1_g,
    const float* __restrict__ W2_g, const float* __restrict__ b2_g,
    const float* __restrict__ mlpW_g, const float* __restrict__ mlpb_g,
    float* __restrict__ out, int B) {
  __shared__ __align__(16) SW sw;
  __shared__ __align__(16) float skv[IMGS][2][TT * 8];

  const int tid = threadIdx.x;

  // ---- stage weights into shared ----
  {
    auto cp = [&](float* d, const float* s, int n) {
      for (int i = tid; i < n; i += NTH) d[i] = s[i];
    };
    cp(sw.linW, linW_g, 128);
    cp(sw.cls, cls_g, 8);
    cp(sw.ln1g, ln1g_g, 32);  cp(sw.ln1b, ln1b_g, 32);
    cp(sw.Wq, Wq_g, 256);     cp(sw.Wk, Wk_g, 256);   cp(sw.Wv, Wv_g, 256);
    cp(sw.projW, projW_g, 256); cp(sw.projb, projb_g, 32);
    cp(sw.ln2g, ln2g_g, 32);  cp(sw.ln2b, ln2b_g, 32);
    cp(sw.W1, W1_g, 1024);    cp(sw.b1, b1_g, 128);
    cp(sw.b2, b2_g, 32);
    cp(sw.mlpW, mlpW_g, 80);
    for (int i = tid; i < 10; i += NTH) sw.mlpb[i] = mlpb_g[i];
    // W2 [blk][8][32] -> transposed [blk][32][8]
    for (int i = tid; i < NB * 256; i += NTH) {
      int blk = i >> 8, rem = i & 255, f = rem >> 3, d = rem & 7;
      sw.W2t[blk * 256 + rem] = W2_g[blk * 256 + d * 32 + f];
    }
    // sinusoidal positional table: 10000^(j/8), j even in {0,2,4,6} -> {1,10,100,1000}
    if (tid < TT) {
      float tf = (float)tid;
      float* p = sw.pos + tid * 8;
      p[0] = sinf(tf);           p[1] = cosf(tf);
      p[2] = sinf(tf * 0.1f);    p[3] = cosf(tf * 0.1f);
      p[4] = sinf(tf * 0.01f);   p[5] = cosf(tf * 0.01f);
      p[6] = sinf(tf * 0.001f);  p[7] = cosf(tf * 0.001f);
    }
  }
  __syncthreads();

  const int img = tid / TPI;
  const int t = tid % TPI;
  const int gb = blockIdx.x * IMGS + img;
  const bool act = (t < TT) && (gb < B);

  float x[8];
  if (act) {
    if (t == 0) {
#pragma unroll
      for (int d = 0; d < 8; d++) x[d] = sw.cls[d] + sw.pos[d];
    } else {
      // patch embed: patch (t-1) -> 4x4 pixels -> lin_W [8][16]
      int p = t - 1, r = p / 7, c = p % 7;
      const float* ip = images + (size_t)gb * 784 + (r * 4) * 28 + c * 4;
      float px[16];
#pragma unroll
      for (int i = 0; i < 4; i++) {
        float4 v4 = *reinterpret_cast<const float4*>(ip + i * 28);
        px[4 * i + 0] = v4.x; px[4 * i + 1] = v4.y;
        px[4 * i + 2] = v4.z; px[4 * i + 3] = v4.w;
      }
#pragma unroll
      for (int d = 0; d < 8; d++) {
        const float* w = sw.linW + d * 16;
        float s = 0.f;
#pragma unroll
        for (int j = 0; j < 16; j++) s = fmaf(px[j], w[j], s);
        x[d] = s + sw.pos[t * 8 + d];
      }
    }
  }

  float* kk = skv[img][0];
  float* vv = skv[img][1];
  const float scale = 0.35355339059327373f;  // 8^-0.5

#pragma unroll 1
  for (int blk = 0; blk < NB; blk++) {
    float q[8];
    if (act) {
      // LN1
      float h[8];
      {
        float mu = 0.f;
#pragma unroll
        for (int d = 0; d < 8; d++) mu += x[d];
        mu *= 0.125f;
        float var = 0.f;
#pragma unroll
        for (int d = 0; d < 8; d++) { float c0 = x[d] - mu; var = fmaf(c0, c0, var); }
        float rs = rsqrtf(var * 0.125f + 1e-5f);
        const float* g = sw.ln1g + blk * 8;
        const float* b = sw.ln1b + blk * 8;
#pragma unroll
        for (int d = 0; d < 8; d++) h[d] = (x[d] - mu) * rs * g[d] + b[d];
      }
      // Q,K,V (row e of W is output dim e)
      const float* wq = sw.Wq + blk * 64;
      const float* wk = sw.Wk + blk * 64;
      const float* wv = sw.Wv + blk * 64;
#pragma unroll
      for (int e = 0; e < 8; e++) q[e] = dot8(h, wq + e * 8);
#pragma unroll
      for (int e = 0; e < 8; e++) kk[t * 8 + e] = dot8(h, wk + e * 8);
#pragma unroll
      for (int e = 0; e < 8; e++) vv[t * 8 + e] = dot8(h, wv + e * 8);
    }
    __syncthreads();

    float o[8];
    if (act) {
      // 2 heads, head size 4; 2-pass softmax (max pass, then exp/accumulate)
#pragma unroll
      for (int hh = 0; hh < 2; hh++) {
        float q0 = q[hh * 4 + 0], q1 = q[hh * 4 + 1];
        float q2 = q[hh * 4 + 2], q3 = q[hh * 4 + 3];
        float m = -1e30f;
        for (int u = 0; u < TT; u++) {
          const float* ku = kk + u * 8 + hh * 4;
          float s = (q0 * ku[0] + q1 * ku[1] + q2 * ku[2] + q3 * ku[3]) * scale;
          m = fmaxf(m, s);
        }
        float l = 0.f, a0 = 0.f, a1 = 0.f, a2 = 0.f, a3 = 0.f;
        for (int u = 0; u < TT; u++) {
          const float* ku = kk + u * 8 + hh * 4;
          const float* vu = vv + u * 8 + hh * 4;
          float s = (q0 * ku[0] + q1 * ku[1] + q2 * ku[2] + q3 * ku[3]) * scale;
          float pw = __expf(s - m);
          l += pw;
          a0 = fmaf(pw, vu[0], a0); a1 = fmaf(pw, vu[1], a1);
          a2 = fmaf(pw, vu[2], a2); a3 = fmaf(pw, vu[3], a3);
        }
        float inv = 1.f / l;
        o[hh * 4 + 0] = a0 * inv; o[hh * 4 + 1] = a1 * inv;
        o[hh * 4 + 2] = a2 * inv; o[hh * 4 + 3] = a3 * inv;
      }
    }
    __syncthreads();  // kv consumed; next block may overwrite

    if (act) {
      // proj + residual
      const float* pw = sw.projW + blk * 64;
      const float* pb = sw.projb + blk * 8;
#pragma unroll
      for (int e = 0; e < 8; e++) x[e] += dot8(o, pw + e * 8) + pb[e];

      // LN2
      float h2[8];
      {
        float mu = 0.f;
#pragma unroll
        for (int d = 0; d < 8; d++) mu += x[d];
        mu *= 0.125f;
        float var = 0.f;
#pragma unroll
        for (int d = 0; d < 8; d++) { float c0 = x[d] - mu; var = fmaf(c0, c0, var); }
        float rs = rsqrtf(var * 0.125f + 1e-5f);
        const float* g = sw.ln2g + blk * 8;
        const float* b = sw.ln2b + blk * 8;
#pragma unroll
        for (int d = 0; d < 8; d++) h2[d] = (x[d] - mu) * rs * g[d] + b[d];
      }
      // MLP 8 -> 32 (relu) -> 8, fused accumulate
      const float* w1 = sw.W1 + blk * 256;
      const float* b1 = sw.b1 + blk * 32;
      const float* w2t = sw.W2t + blk * 256;
      const float* b2 = sw.b2 + blk * 8;
      float acc[8];
#pragma unroll
      for (int d = 0; d < 8; d++) acc[d] = 0.f;
#pragma unroll 4
      for (int f = 0; f < 32; f++) {
        float ff = b1[f] + dot8(h2, w1 + f * 8);
        ff = fmaxf(ff, 0.f);
        const float* wr = w2t + f * 8;
#pragma unroll
        for (int d = 0; d < 8; d++) acc[d] = fmaf(ff, wr[d], acc[d]);
      }
#pragma unroll
      for (int d = 0; d < 8; d++) x[d] += acc[d] + b2[d];
    }
  }

  // classification head on token 0: softmax(x0 @ mlpW^T + mlpb)
  if (act && t == 0) {
    float z[10];
    float zm = -1e30f;
#pragma unroll
    for (int c = 0; c < 10; c++) {
      float s = sw.mlpb[c] + dot8(x, sw.mlpW + c * 8);
      z[c] = s;
      zm = fmaxf(zm, s);
    }
    float ssum = 0.f;
#pragma unroll
    for (int c = 0; c < 10; c++) { z[c] = __expf(z[c] - zm); ssum += z[c]; }
    float inv = 1.f / ssum;
#pragma unroll
    for (int c = 0; c < 10; c++) out[gb * 10 + c] = z[c] * inv;
  }
}

extern "C" void kernel_launch(void* const* d_in, const int* in_sizes, int n_in,
                              void* d_out, int out_size) {
  const float* images = (const float*)d_in[0];
  const float* cls    = (const float*)d_in[1];
  const float* linW   = (const float*)d_in[2];
  const float* ln1g   = (const float*)d_in[3];
  const float* ln1b   = (const float*)d_in[4];
  const float* Wq     = (const float*)d_in[5];
  const float* Wk     = (const float*)d_in[6];
  const float* Wv     = (const float*)d_in[7];
  const float* projW  = (const float*)d_in[8];
  const float* projb  = (const float*)d_in[9];
  const float* ln2g   = (const float*)d_in[10];
  const float* ln2b   = (const float*)d_in[11];
  const float* W1     = (const float*)d_in[12];
  const float* b1     = (const float*)d_in[13];
  const float* W2     = (const float*)d_in[14];
  const float* b2     = (const float*)d_in[15];
  const float* mlpW   = (const float*)d_in[16];
  const float* mlpb   = (const float*)d_in[17];

  int B = in_sizes[0] / 784;
  dim3 grid((B + IMGS - 1) / IMGS);
  vit_kernel<<<grid, NTH>>>(images, cls, linW, ln1g, ln1b, Wq, Wk, Wv, projW,
                            projb, ln2g, ln2b, W1, b1, W2, b2, mlpW, mlpb,
                            (float*)d_out, B);
}